// round 16
// baseline (speedup 1.0000x reference)
#include <cuda_runtime.h>
#include <cuda_fp16.h>
#include <cstdint>

// Problem constants (from reference)
#define BATCH 16384
#define EMBED 1024
#define SEQ   7
#define E4    (EMBED / 4)       // 256 float4 lanes per full row
#define EQ4   64                // float4 lanes per quarter (256 channels)
#define NQ    4                 // channel quarters (grid.y)
#define ROWS_PER_CTA 8
#define ROWS_PER_IT  2          // 128 threads / 64 lanes
#define NIT  (ROWS_PER_CTA / ROWS_PER_IT)   // 4
#define THREADS 128
#define ROW_BYTES   (EQ4 * 16)                        // 1KB per quarter-row
#define STAGE_BYTES (ROWS_PER_IT * SEQ * ROW_BYTES)   // 14,336 B per stage

// reinterpret helpers
__device__ __forceinline__ __half2 u2h2(unsigned r) {
    __half2 h; *reinterpret_cast<unsigned*>(&h) = r; return h;
}
__device__ __forceinline__ unsigned h22u(__half2 h) {
    return *reinterpret_cast<unsigned*>(&h);
}
// packed f16x2 tanh: one MUFU op for two channels
__device__ __forceinline__ __half2 tanh2h(__half2 x) {
    unsigned r = h22u(x);
    asm("tanh.approx.f16x2 %0, %0;" : "+r"(r));
    return u2h2(r);
}
__device__ __forceinline__ __half2 mk2(float a, float b, float s) {
    return __floats2half2_rn(a * s, b * s);
}
__device__ __forceinline__ uint32_t smem_u32(const void* p) {
    uint32_t a;
    asm("{ .reg .u64 t; cvta.to.shared.u64 t, %1; cvt.u32.u64 %0, t; }"
        : "=r"(a) : "l"(p));
    return a;
}
// blocking mbarrier parity wait (acquire) with sleep-based retry
__device__ __forceinline__ void mbar_wait(uint32_t mbar, uint32_t parity) {
    uint32_t done;
    asm volatile(
        "{\n\t"
        ".reg .pred P;\n\t"
        "mbarrier.try_wait.parity.acquire.cta.shared::cta.b64 P, [%1], %2, 0x989680;\n\t"
        "selp.b32 %0, 1, 0, P;\n\t"
        "}"
        : "=r"(done) : "r"(mbar), "r"(parity) : "memory");
    while (!done) {
        __nanosleep(32);
        asm volatile(
            "{\n\t"
            ".reg .pred P;\n\t"
            "mbarrier.try_wait.parity.acquire.cta.shared::cta.b64 P, [%1], %2, 0x989680;\n\t"
            "selp.b32 %0, 1, 0, P;\n\t"
            "}"
            : "=r"(done) : "r"(mbar), "r"(parity) : "memory");
    }
}

// TMA-bulk gather pipeline: thread 0 issues 14 x 1KB cp.async.bulk copies per
// stage (emb quarter-rows -> smem), tracked by mbarrier expect_tx; all threads
// consume via LDS. Gathers never touch the L1tex miss-tracking path.
__global__ void __launch_bounds__(THREADS, 7)
conv_cascade_q_kernel(const int* __restrict__ X,
                      const float4* __restrict__ emb,   // (VOCAB, E4)
                      const float4* __restrict__ c1,    // (2, E4)
                      const float4* __restrict__ c2,    // (2, E4)
                      const float4* __restrict__ c3,    // (3, E4)
                      const float4* __restrict__ c4,    // (3, E4)
                      float4* __restrict__ out)         // (BATCH, E4)
{
    const int tid  = threadIdx.x;
    const int lane = tid & (EQ4 - 1);                   // 0..63
    const int rsub = tid >> 6;                          // 0..1 row within iter
    const int e4   = blockIdx.y * EQ4 + lane;
    const int b0   = blockIdx.x * ROWS_PER_CTA;

    __shared__ float4 buf[2][ROWS_PER_IT][SEQ][EQ4];    // 28,672 B
    __shared__ int    idx[ROWS_PER_CTA][SEQ];
    __shared__ __align__(8) unsigned long long mbar[2];

    if (tid < ROWS_PER_CTA * SEQ) {
        int r = tid / SEQ;
        int t = tid % SEQ;
        idx[r][t] = X[(b0 + r) * SEQ + t];
    }
    if (tid == 0) {
        uint32_t m0 = smem_u32(&mbar[0]);
        asm volatile("mbarrier.init.shared.b64 [%0], 1;" :: "r"(m0) : "memory");
        asm volatile("mbarrier.init.shared.b64 [%0], 1;" :: "r"(m0 + 8) : "memory");
    }

    // Tanh-domain scaled weights in registers (f16x2; a = ch0/1, b = ch2/3).
    float4 a0 = c1[0 * E4 + e4], a1 = c1[1 * E4 + e4];
    float4 d0 = c2[0 * E4 + e4], d1 = c2[1 * E4 + e4];
    float4 e0 = c3[0 * E4 + e4], e1 = c3[1 * E4 + e4], e2 = c3[2 * E4 + e4];
    float4 f0 = c4[0 * E4 + e4], f1 = c4[1 * E4 + e4], f2 = c4[2 * E4 + e4];

    const __half2 W10a = mk2(a0.x, a0.y, 0.5f),  W10b = mk2(a0.z, a0.w, 0.5f);
    const __half2 W11a = mk2(a1.x, a1.y, 0.5f),  W11b = mk2(a1.z, a1.w, 0.5f);
    const __half2 V0a  = mk2(d0.x, d0.y, 0.25f), V0b  = mk2(d0.z, d0.w, 0.25f);
    const __half2 V1a  = mk2(d1.x, d1.y, 0.25f), V1b  = mk2(d1.z, d1.w, 0.25f);
    const __half2 B2a  = mk2(d0.x + d1.x, d0.y + d1.y, 0.25f);
    const __half2 B2b  = mk2(d0.z + d1.z, d0.w + d1.w, 0.25f);
    const __half2 U0a  = mk2(e0.x, e0.y, 0.25f), U0b  = mk2(e0.z, e0.w, 0.25f);
    const __half2 U1a  = mk2(e1.x, e1.y, 0.25f), U1b  = mk2(e1.z, e1.w, 0.25f);
    const __half2 U2a  = mk2(e2.x, e2.y, 0.25f), U2b  = mk2(e2.z, e2.w, 0.25f);
    const __half2 B3a  = mk2(e0.x + e1.x + e2.x, e0.y + e1.y + e2.y, 0.25f);
    const __half2 B3b  = mk2(e0.z + e1.z + e2.z, e0.w + e1.w + e2.w, 0.25f);
    const __half2 T0a  = mk2(f0.x, f0.y, 0.25f), T0b  = mk2(f0.z, f0.w, 0.25f);
    const __half2 T1a  = mk2(f1.x, f1.y, 0.25f), T1b  = mk2(f1.z, f1.w, 0.25f);
    const __half2 T2a  = mk2(f2.x, f2.y, 0.25f), T2b  = mk2(f2.z, f2.w, 0.25f);
    const __half2 B4a  = mk2(f0.x + f1.x + f2.x, f0.y + f1.y + f2.y, 0.25f);
    const __half2 B4b  = mk2(f0.z + f1.z + f2.z, f0.w + f1.w + f2.w, 0.25f);
    const __half2 HALF = __float2half2_rn(0.5f);

    __syncthreads();   // idx + mbarrier init visible

    const uint32_t mb0   = smem_u32(&mbar[0]);
    const int      qbase = blockIdx.y * EQ4;

    // Issue the stage's 14 x 1KB bulk copies (thread 0 only).
    auto issue = [&](int it, int stage) {
        if (tid == 0) {
            uint32_t mb = mb0 + stage * 8;
            asm volatile("mbarrier.arrive.expect_tx.shared.b64 _, [%0], %1;"
                         :: "r"(mb), "r"((uint32_t)STAGE_BYTES) : "memory");
#pragma unroll
            for (int rr = 0; rr < ROWS_PER_IT; ++rr) {
#pragma unroll
                for (int t = 0; t < SEQ; ++t) {
                    const float4* src =
                        &emb[(long)idx[it * ROWS_PER_IT + rr][t] * E4 + qbase];
                    uint32_t dst = smem_u32(&buf[stage][rr][t][0]);
                    asm volatile(
                        "cp.async.bulk.shared::cta.global"
                        ".mbarrier::complete_tx::bytes [%0], [%1], %2, [%3];"
                        :: "r"(dst), "l"(src), "r"((uint32_t)ROW_BYTES), "r"(mb)
                        : "memory");
                }
            }
        }
    };

    issue(0, 0);   // prologue

#pragma unroll 1
    for (int it = 0; it < NIT; ++it) {
        const int stage  = it & 1;
        const int parity = (it >> 1) & 1;

        mbar_wait(mb0 + stage * 8, (uint32_t)parity);

        // Consume this thread's 7 staged float4s -> half2.
        __half2 ha[SEQ], hb[SEQ];
#pragma unroll
        for (int t = 0; t < SEQ; ++t) {
            float4 v = buf[stage][rsub][t][lane];
            ha[t] = __floats2half2_rn(v.x, v.y);
            hb[t] = __floats2half2_rn(v.z, v.w);
        }

        __syncthreads();               // all warps done with stage (and stage^1)
        if (it + 1 < NIT) issue(it + 1, stage ^ 1);

        // Stage 1 (size-2, raw input, scale 1/2, no bias)
        __half2 pa[6], pb[6];
#pragma unroll
        for (int t = 0; t < 6; ++t) {
            pa[t] = tanh2h(__hfma2(W10a, ha[t], __hmul2(W11a, ha[t + 1])));
            pb[t] = tanh2h(__hfma2(W10b, hb[t], __hmul2(W11b, hb[t + 1])));
        }

        // Stage 2 (size-2, tanh-domain, scale 1/4 + bias)
        __half2 qa[5], qb[5];
#pragma unroll
        for (int t = 0; t < 5; ++t) {
            qa[t] = tanh2h(__hfma2(V0a, pa[t], __hfma2(V1a, pa[t + 1], B2a)));
            qb[t] = tanh2h(__hfma2(V0b, pb[t], __hfma2(V1b, pb[t + 1], B2b)));
        }

        // Stage 3 (size-3)
        __half2 sa[3], sb[3];
#pragma unroll
        for (int t = 0; t < 3; ++t) {
            sa[t] = tanh2h(__hfma2(U0a, qa[t],
                        __hfma2(U1a, qa[t + 1], __hfma2(U2a, qa[t + 2], B3a))));
            sb[t] = tanh2h(__hfma2(U0b, qb[t],
                        __hfma2(U1b, qb[t + 1], __hfma2(U2b, qb[t + 2], B3b))));
        }

        // Stage 4 (size-3) + final affine back to sigma
        __half2 ra = tanh2h(__hfma2(T0a, sa[0],
                       __hfma2(T1a, sa[1], __hfma2(T2a, sa[2], B4a))));
        __half2 rb = tanh2h(__hfma2(T0b, sb[0],
                       __hfma2(T1b, sb[1], __hfma2(T2b, sb[2], B4b))));
        ra = __hfma2(ra, HALF, HALF);
        rb = __hfma2(rb, HALF, HALF);

        float2 fa = __half22float2(ra);
        float2 fb = __half22float2(rb);
        const int r = it * ROWS_PER_IT + rsub;
        __stcs(&out[(long)(b0 + r) * E4 + e4],
               make_float4(fa.x, fa.y, fb.x, fb.y));
    }
}

extern "C" void kernel_launch(void* const* d_in, const int* in_sizes, int n_in,
                              void* d_out, int out_size)
{
    const int*    X    = (const int*)d_in[0];
    const float4* emb  = (const float4*)d_in[1];
    const float4* c1   = (const float4*)d_in[2];
    const float4* c2   = (const float4*)d_in[3];
    const float4* c3   = (const float4*)d_in[4];
    const float4* c4   = (const float4*)d_in[5];
    float4*       out  = (float4*)d_out;

    dim3 grid(BATCH / ROWS_PER_CTA, NQ);   // (2048, 4) — x fastest => quarter order
    dim3 block(THREADS);
    conv_cascade_q_kernel<<<grid, block>>>(X, emb, c1, c2, c3, c4, out);
}

// round 17
// speedup vs baseline: 1.0310x; 1.0310x over previous
#include <cuda_runtime.h>
#include <cuda_fp16.h>
#include <cstdint>

// Problem constants (from reference)
#define BATCH 16384
#define EMBED 1024
#define SEQ   7
#define E4    (EMBED / 4)       // 256 float4 lanes per full row
#define EQ4   64                // float4 lanes per quarter (256 channels)
#define NQ    4                 // channel quarters (grid.y)
#define ROWS_PER_CTA 32
#define ROWS_PER_IT  4          // 256 threads / 64 lanes
#define NIT (ROWS_PER_CTA / ROWS_PER_IT)   // 8
#define THREADS 256

// reinterpret helpers
__device__ __forceinline__ __half2 u2h2(unsigned r) {
    __half2 h; *reinterpret_cast<unsigned*>(&h) = r; return h;
}
__device__ __forceinline__ unsigned h22u(__half2 h) {
    return *reinterpret_cast<unsigned*>(&h);
}
// packed f16x2 tanh: one MUFU op for two channels
__device__ __forceinline__ __half2 tanh2h(__half2 x) {
    unsigned r = h22u(x);
    asm("tanh.approx.f16x2 %0, %0;" : "+r"(r));
    return u2h2(r);
}
// scaled float pair -> half2
__device__ __forceinline__ __half2 mk2(float a, float b, float s) {
    return __floats2half2_rn(a * s, b * s);
}

// blockIdx.y = channel quarter; blockIdx.x walks the batch (x-fastest order
// keeps each quarter's 32.7MB gather footprint L2-resident).
__global__ void __launch_bounds__(THREADS, 4)
conv_cascade_q_kernel(const int* __restrict__ X,
                      const float4* __restrict__ emb,   // (VOCAB, E4)
                      const float4* __restrict__ c1,    // (2, E4)
                      const float4* __restrict__ c2,    // (2, E4)
                      const float4* __restrict__ c3,    // (3, E4)
                      const float4* __restrict__ c4,    // (3, E4)
                      float4* __restrict__ out)         // (BATCH, E4)
{
    const int lane = threadIdx.x & (EQ4 - 1);           // 0..63
    const int rsub = threadIdx.x >> 6;                  // 0..3
    const int e4   = blockIdx.y * EQ4 + lane;
    const int b0   = blockIdx.x * ROWS_PER_CTA;

    __shared__ int idx[ROWS_PER_CTA][SEQ];
    if (threadIdx.x < ROWS_PER_CTA * SEQ) {
        int r = threadIdx.x / SEQ;
        int t = threadIdx.x % SEQ;
        idx[r][t] = X[(b0 + r) * SEQ + t];
    }

    // Tanh-domain scaled weights, ALL in registers (f16x2; a = ch0/1, b = ch2/3).
    // Stage1: w/2 no bias; stages 2-4: w/4 with bias = sum(w)/4.
    float4 a0 = c1[0 * E4 + e4], a1 = c1[1 * E4 + e4];
    float4 d0 = c2[0 * E4 + e4], d1 = c2[1 * E4 + e4];
    float4 e0 = c3[0 * E4 + e4], e1 = c3[1 * E4 + e4], e2 = c3[2 * E4 + e4];
    float4 f0 = c4[0 * E4 + e4], f1 = c4[1 * E4 + e4], f2 = c4[2 * E4 + e4];

    const __half2 W10a = mk2(a0.x, a0.y, 0.5f),  W10b = mk2(a0.z, a0.w, 0.5f);
    const __half2 W11a = mk2(a1.x, a1.y, 0.5f),  W11b = mk2(a1.z, a1.w, 0.5f);
    const __half2 V0a  = mk2(d0.x, d0.y, 0.25f), V0b  = mk2(d0.z, d0.w, 0.25f);
    const __half2 V1a  = mk2(d1.x, d1.y, 0.25f), V1b  = mk2(d1.z, d1.w, 0.25f);
    const __half2 B2a  = mk2(d0.x + d1.x, d0.y + d1.y, 0.25f);
    const __half2 B2b  = mk2(d0.z + d1.z, d0.w + d1.w, 0.25f);
    const __half2 U0a  = mk2(e0.x, e0.y, 0.25f), U0b  = mk2(e0.z, e0.w, 0.25f);
    const __half2 U1a  = mk2(e1.x, e1.y, 0.25f), U1b  = mk2(e1.z, e1.w, 0.25f);
    const __half2 U2a  = mk2(e2.x, e2.y, 0.25f), U2b  = mk2(e2.z, e2.w, 0.25f);
    const __half2 B3a  = mk2(e0.x + e1.x + e2.x, e0.y + e1.y + e2.y, 0.25f);
    const __half2 B3b  = mk2(e0.z + e1.z + e2.z, e0.w + e1.w + e2.w, 0.25f);
    const __half2 T0a  = mk2(f0.x, f0.y, 0.25f), T0b  = mk2(f0.z, f0.w, 0.25f);
    const __half2 T1a  = mk2(f1.x, f1.y, 0.25f), T1b  = mk2(f1.z, f1.w, 0.25f);
    const __half2 T2a  = mk2(f2.x, f2.y, 0.25f), T2b  = mk2(f2.z, f2.w, 0.25f);
    const __half2 B4a  = mk2(f0.x + f1.x + f2.x, f0.y + f1.y + f2.y, 0.25f);
    const __half2 B4b  = mk2(f0.z + f1.z + f2.z, f0.w + f1.w + f2.w, 0.25f);
    const __half2 HALF = __float2half2_rn(0.5f);

    __syncthreads();

#pragma unroll 2
    for (int it = 0; it < NIT; ++it) {
        const int r = it * ROWS_PER_IT + rsub;

        // Gather 7 embedding float4s -> f16x2 pairs (edge conversion only).
        __half2 ha[SEQ], hb[SEQ];
#pragma unroll
        for (int t = 0; t < SEQ; ++t) {
            long row = (long)idx[r][t];
            float4 h = __ldg(&emb[row * E4 + e4]);
            ha[t] = __floats2half2_rn(h.x, h.y);
            hb[t] = __floats2half2_rn(h.z, h.w);
        }

        // Stage 1 (size-2, raw input, scale 1/2, no bias)
        __half2 pa[6], pb[6];
#pragma unroll
        for (int t = 0; t < 6; ++t) {
            pa[t] = tanh2h(__hfma2(W10a, ha[t], __hmul2(W11a, ha[t + 1])));
            pb[t] = tanh2h(__hfma2(W10b, hb[t], __hmul2(W11b, hb[t + 1])));
        }

        // Stage 2 (size-2, tanh-domain, scale 1/4 + bias)
        __half2 qa[5], qb[5];
#pragma unroll
        for (int t = 0; t < 5; ++t) {
            qa[t] = tanh2h(__hfma2(V0a, pa[t], __hfma2(V1a, pa[t + 1], B2a)));
            qb[t] = tanh2h(__hfma2(V0b, pb[t], __hfma2(V1b, pb[t + 1], B2b)));
        }

        // Stage 3 (size-3)
        __half2 sa[3], sb[3];
#pragma unroll
        for (int t = 0; t < 3; ++t) {
            sa[t] = tanh2h(__hfma2(U0a, qa[t],
                        __hfma2(U1a, qa[t + 1], __hfma2(U2a, qa[t + 2], B3a))));
            sb[t] = tanh2h(__hfma2(U0b, qb[t],
                        __hfma2(U1b, qb[t + 1], __hfma2(U2b, qb[t + 2], B3b))));
        }

        // Stage 4 (size-3) + final affine back to sigma
        __half2 ra = tanh2h(__hfma2(T0a, sa[0],
                       __hfma2(T1a, sa[1], __hfma2(T2a, sa[2], B4a))));
        __half2 rb = tanh2h(__hfma2(T0b, sb[0],
                       __hfma2(T1b, sb[1], __hfma2(T2b, sb[2], B4b))));
        ra = __hfma2(ra, HALF, HALF);
        rb = __hfma2(rb, HALF, HALF);

        float2 fa = __half22float2(ra);
        float2 fb = __half22float2(rb);
        __stcs(&out[(long)(b0 + r) * E4 + e4],
               make_float4(fa.x, fa.y, fb.x, fb.y));
    }
}

extern "C" void kernel_launch(void* const* d_in, const int* in_sizes, int n_in,
                              void* d_out, int out_size)
{
    const int*    X    = (const int*)d_in[0];
    const float4* emb  = (const float4*)d_in[1];
    const float4* c1   = (const float4*)d_in[2];
    const float4* c2   = (const float4*)d_in[3];
    const float4* c3   = (const float4*)d_in[4];
    const float4* c4   = (const float4*)d_in[5];
    float4*       out  = (float4*)d_out;

    dim3 grid(BATCH / ROWS_PER_CTA, NQ);   // (512, 4) — x fastest => quarter order
    dim3 block(THREADS);
    conv_cascade_q_kernel<<<grid, block>>>(X, emb, c1, c2, c3, c4, out);
}